// round 16
// baseline (speedup 1.0000x reference)
#include <cuda_runtime.h>
#include <cuda_fp16.h>
#include <cstdint>

// Spatial RNN, 4 dirs, R=8 steps, C=64. f16 mma.sync, fully register-resident.
// x:(8,192,192,64) fp32; W_*:(64,64); out:(8,192,192,256)
//
// v-form: v_s = relu(W v_{s-1}), v_0 = x (no shift; C-frag packing == A-frag
// packing -> chain is a register rename, no smem). Shifted-prefix accumulator:
// S_k(r) = v_k(r) + S_{k-1}(r+d) (constant 1-row shift via lane+-4 shuffles +
// one 32B smem edge word per warp boundary), acc(o) = S_8(o - 8*d).
// One CTA per line: 13 warps (416 thr), warp tile m16 x n64, rows 16w-8
// covering [-8..199]. One __syncthreads per step gating only the edge words.

#define THREADS 416
#define EPAR (14 * 128)              // one parity region: 14 slots x 128B
#define SMEM_DYN (4 * EPAR + 64)     // dir0[2 par] + dir1[2 par]

static __device__ __forceinline__ uint32_t smem_u32(const void* p) {
    uint32_t a;
    asm("{ .reg .u64 t; cvta.to.shared.u64 t, %1; cvt.u32.u64 %0, t; }" : "=r"(a) : "l"(p));
    return a;
}
static __device__ __forceinline__ uint32_t pkh2(float lo, float hi) {
    uint32_t r;
    asm("cvt.rn.f16x2.f32 %0, %1, %2;" : "=r"(r) : "f"(hi), "f"(lo));
    return r;
}
static __device__ __forceinline__ uint32_t hmax2z(uint32_t v) {
    uint32_t r;
    asm("max.f16x2 %0, %1, %2;" : "=r"(r) : "r"(v), "r"(0u));
    return r;
}
static __device__ __forceinline__ uint32_t hadd2(uint32_t a, uint32_t b) {
    uint32_t r;
    asm("add.f16x2 %0, %1, %2;" : "=r"(r) : "r"(a), "r"(b));
    return r;
}
static __device__ __forceinline__ void unpkh2(uint32_t v, float& lo, float& hi) {
    asm("{ .reg .f16 l, h; mov.b32 {l, h}, %2; cvt.f32.f16 %0, l; cvt.f32.f16 %1, h; }"
        : "=f"(lo), "=f"(hi) : "r"(v));
}
static __device__ __forceinline__ void mma16816h(uint32_t c[2], const uint32_t a[4],
                                                 const uint32_t b[2]) {
    asm volatile(
        "mma.sync.aligned.m16n8k16.row.col.f16.f16.f16.f16 "
        "{%0,%1}, {%2,%3,%4,%5}, {%6,%7}, {%0,%1};"
        : "+r"(c[0]), "+r"(c[1])
        : "r"(a[0]), "r"(a[1]), "r"(a[2]), "r"(a[3]), "r"(b[0]), "r"(b[1]));
}
static __device__ __forceinline__ void sts32(uint32_t addr, uint32_t v) {
    asm volatile("st.shared.b32 [%0], %1;" :: "r"(addr), "r"(v) : "memory");
}
static __device__ __forceinline__ uint32_t lds32(uint32_t addr) {
    uint32_t v;
    asm volatile("ld.shared.b32 %0, [%1];" : "=r"(v) : "r"(addr));
    return v;
}

extern "C" __global__ void __launch_bounds__(THREADS, 1)
rnn_kernel(const float* __restrict__ x,
           const float* __restrict__ W_left, const float* __restrict__ W_right,
           const float* __restrict__ W_up,   const float* __restrict__ W_down,
           float* __restrict__ out)
{
    extern __shared__ char dsm[];
    const uint32_t base = (smem_u32(dsm) + 15u) & ~15u;
    const uint32_t E0 = base;              // dir0 edges, guard = slot 13
    const uint32_t E1 = base + 2 * EPAR;   // dir1 edges, guard = slot 0

    const int tid  = threadIdx.x;
    const int lane = tid & 31;
    const int warp = tid >> 5;             // 0..12, row base = 16*warp - 8
    const int gID  = lane >> 2;
    const int tg   = lane & 3;

    // --- geometry ---
    long inBase, outBase;
    int pixIn, pixOut, chBase;
    const float *Wfp, *Wbp;
    {
        int l = blockIdx.x;
        if (l < 1536) {                            // horizontal row
            inBase  = (long)l * (192 * 64);
            outBase = (long)l * (192 * 256);
            pixIn = 64;  pixOut = 256;  chBase = 0;
            Wfp = W_left;  Wbp = W_right;
        } else {                                    // vertical column
            int l2 = l - 1536;
            int b = l2 / 192, w = l2 % 192;
            inBase  = (long)b * (192 * 192 * 64)  + (long)w * 64;
            outBase = (long)b * (192 * 192 * 256) + (long)w * 256;
            pixIn = 192 * 64;  pixOut = 192 * 256;  chBase = 128;
            Wfp = W_up;  Wbp = W_down;
        }
    }
    const float* xl = x + inBase;
    float* ol = out + outBase;

    // --- zero the static guard edge slots (dir0 slot 13, dir1 slot 0) ---
    if (tid < 32) {
        sts32(E0 + 13 * 128 + tid * 4, 0);
        sts32(E0 + EPAR + 13 * 128 + tid * 4, 0);
        sts32(E1 + tid * 4, 0);
        sts32(E1 + EPAR + tid * 4, 0);
    }
    __syncthreads();

    const int r0 = 16 * warp - 8 + gID;    // row for fragment reg[0]
    const int r1 = r0 + 8;                 // row for fragment reg[1]
    const bool ok0 = ((unsigned)r0 < 192u);
    const bool ok1 = ((unsigned)r1 < 192u);
    const float* p0 = xl + (long)r0 * pixIn + 2 * tg;
    const float* p1 = xl + (long)r1 * pixIn + 2 * tg;

    #pragma unroll
    for (int dir = 0; dir < 2; dir++) {
        const float* Wg = dir ? Wbp : Wfp;

        // --- B fragments (n64 x k64) in registers, from gmem (L2-hot) ---
        uint32_t b[4][8][2];
        #pragma unroll
        for (int kc = 0; kc < 4; kc++)
            #pragma unroll
            for (int nt = 0; nt < 8; nt++) {
                int k0 = kc * 16 + 2 * tg;
                int n  = nt * 8 + gID;
                b[kc][nt][0] = pkh2(__ldg(&Wg[(k0)     * 64 + n]), __ldg(&Wg[(k0 + 1) * 64 + n]));
                b[kc][nt][1] = pkh2(__ldg(&Wg[(k0 + 8) * 64 + n]), __ldg(&Wg[(k0 + 9) * 64 + n]));
            }

        // --- a = v_0 = x (predicated; rows outside [0,192) are zero) ---
        uint32_t a[4][4];
        #pragma unroll
        for (int kc = 0; kc < 4; kc++) {
            float2 z00 = ok0 ? *reinterpret_cast<const float2*>(p0 + kc * 16)     : make_float2(0.f, 0.f);
            float2 z01 = ok0 ? *reinterpret_cast<const float2*>(p0 + kc * 16 + 8) : make_float2(0.f, 0.f);
            float2 z10 = ok1 ? *reinterpret_cast<const float2*>(p1 + kc * 16)     : make_float2(0.f, 0.f);
            float2 z11 = ok1 ? *reinterpret_cast<const float2*>(p1 + kc * 16 + 8) : make_float2(0.f, 0.f);
            a[kc][0] = pkh2(z00.x, z00.y);
            a[kc][1] = pkh2(z10.x, z10.y);
            a[kc][2] = pkh2(z01.x, z01.y);
            a[kc][3] = pkh2(z11.x, z11.y);
        }

        uint32_t S[8][2];
        #pragma unroll
        for (int nt = 0; nt < 8; nt++) { S[nt][0] = 0u; S[nt][1] = 0u; }

        #pragma unroll 2
        for (int s = 1; s <= 8; s++) {
            const uint32_t par = (uint32_t)(s & 1) * EPAR;

            // phase 1: publish the S_old edge row (one 32B word-set per warp)
            if (dir == 0) {
                if (gID == 0) {                    // row base -> consumed by warp-1
                    uint32_t ea = E0 + par + (uint32_t)(warp * 128) + tg * 4;
                    #pragma unroll
                    for (int nt = 0; nt < 8; nt++) sts32(ea + nt * 16, S[nt][0]);
                }
            } else {
                if (gID == 7) {                    // row base+15 -> consumed by warp+1
                    uint32_t ea = E1 + par + (uint32_t)((warp + 1) * 128) + tg * 4;
                    #pragma unroll
                    for (int nt = 0; nt < 8; nt++) sts32(ea + nt * 16, S[nt][1]);
                }
            }

            // phase 2: v_s = relu(W v_{s-1}) — pure register chain
            uint32_t Cf[8][2];
            #pragma unroll
            for (int nt = 0; nt < 8; nt++) { Cf[nt][0] = 0u; Cf[nt][1] = 0u; }
            #pragma unroll
            for (int kc = 0; kc < 4; kc++)
                #pragma unroll
                for (int nt = 0; nt < 8; nt++)
                    mma16816h(Cf[nt], a[kc], b[kc][nt]);
            #pragma unroll
            for (int nt = 0; nt < 8; nt++) {
                Cf[nt][0] = hmax2z(Cf[nt][0]);
                Cf[nt][1] = hmax2z(Cf[nt][1]);
            }

            __syncthreads();                       // edge words visible

            // phase 4: S_new(r) = v_s(r) + S_old(r + d)
            if (dir == 0) {                        // d = +1: rows from below
                uint32_t er = E0 + par + (uint32_t)((warp + 1) * 128) + tg * 4;
                #pragma unroll
                for (int nt = 0; nt < 8; nt++) {
                    uint32_t d0 = __shfl_down_sync(0xffffffffu, S[nt][0], 4);
                    uint32_t d1 = __shfl_down_sync(0xffffffffu, S[nt][1], 4);
                    uint32_t sp = __shfl_sync(0xffffffffu, S[nt][1], tg);       // row base+8
                    uint32_t e  = lds32(er + nt * 16);                          // row base+16
                    S[nt][0] = hadd2(Cf[nt][0], (gID == 7) ? sp : d0);
                    S[nt][1] = hadd2(Cf[nt][1], (gID == 7) ? e  : d1);
                }
            } else {                               // d = -1: rows from above
                uint32_t er = E1 + par + (uint32_t)(warp * 128) + tg * 4;
                #pragma unroll
                for (int nt = 0; nt < 8; nt++) {
                    uint32_t u0 = __shfl_up_sync(0xffffffffu, S[nt][0], 4);
                    uint32_t u1 = __shfl_up_sync(0xffffffffu, S[nt][1], 4);
                    uint32_t sp = __shfl_sync(0xffffffffu, S[nt][0], 28 + tg);  // row base+7
                    uint32_t e  = lds32(er + nt * 16);                          // row base-1
                    S[nt][0] = hadd2(Cf[nt][0], (gID == 0) ? e  : u0);
                    S[nt][1] = hadd2(Cf[nt][1], (gID == 0) ? sp : u1);
                }
            }

            // phase 5: rename a <- v_s (C-frag packing == A-frag packing)
            #pragma unroll
            for (int kc = 0; kc < 4; kc++) {
                a[kc][0] = Cf[2 * kc][0];
                a[kc][1] = Cf[2 * kc][1];
                a[kc][2] = Cf[2 * kc + 1][0];
                a[kc][3] = Cf[2 * kc + 1][1];
            }
        }

        // --- epilogue: out(o) = x(o) + S_8(o - 8d); o = r -+ 8 ---
        const int cb = chBase + dir * 64;
        const bool wr = dir ? (warp >= 1) : (warp < 12);
        const int ob = dir ? (16 * (warp - 1)) : (16 * warp);
        if (wr) {
            #pragma unroll
            for (int hh = 0; hh < 2; hh++) {
                int o = ob + gID + 8 * hh;
                const float* xp = xl + (long)o * pixIn;
                float* op = ol + (long)o * pixOut + cb;
                #pragma unroll
                for (int nt = 0; nt < 8; nt++) {
                    int col = nt * 8 + 2 * tg;
                    float v0, v1;
                    unpkh2(S[nt][hh], v0, v1);
                    float2 xv = *reinterpret_cast<const float2*>(xp + col);
                    *reinterpret_cast<float2*>(op + col) =
                        make_float2(xv.x + v0, xv.y + v1);
                }
            }
        }
        // no cross-dir barrier needed: the dirs use disjoint edge regions and
        // barrier instances are totally ordered across the CTA.
    }
}

extern "C" void kernel_launch(void* const* d_in, const int* in_sizes, int n_in,
                              void* d_out, int out_size)
{
    const float* x  = (const float*)d_in[0];
    const float* wl = (const float*)d_in[1];
    const float* wr = (const float*)d_in[2];
    const float* wu = (const float*)d_in[3];
    const float* wd = (const float*)d_in[4];
    float* out = (float*)d_out;

    cudaFuncSetAttribute(rnn_kernel, cudaFuncAttributeMaxDynamicSharedMemorySize, SMEM_DYN);
    rnn_kernel<<<3072, THREADS, SMEM_DYN>>>(x, wl, wr, wu, wd, out);
}

// round 17
// speedup vs baseline: 1.3781x; 1.3781x over previous
#include <cuda_runtime.h>
#include <cuda_fp16.h>
#include <cstdint>

// Spatial RNN, 4 dirs, R=8 steps, C=64. f16 mma.sync (f16 accum) + LDSM/STSM.
// x:(8,192,192,64) fp32; W_*:(64,64); out:(8,192,192,256)
//
// R17 = R13 split per-direction: one CTA handles ONE direction of one scan
// line (grid 3072 x 2, 128 thr, 4 warps, m48 x n64 warp tiles, zero A dup).
// x loads straight into ping-pong buffer P0 (no separate Xb), so smem is
// 2 x 24832B = 49.7KB and regs ~126 -> 4 CTAs/SM (16 warps, 4 independent
// barrier domains). SW128-swizzled 128B-stride buffers; packed f16x2
// accumulators; B in registers from L2-hot gmem.

#define BUFB (194 * 128)            // 24832 bytes per buffer
#define SMEM_DYN (2 * BUFB + 64)    // 49728

static __device__ __forceinline__ uint32_t smem_u32(const void* p) {
    uint32_t a;
    asm("{ .reg .u64 t; cvta.to.shared.u64 t, %1; cvt.u32.u64 %0, t; }" : "=r"(a) : "l"(p));
    return a;
}
static __device__ __forceinline__ uint32_t pkh2(float lo, float hi) {
    uint32_t r;
    asm("cvt.rn.f16x2.f32 %0, %1, %2;" : "=r"(r) : "f"(hi), "f"(lo));
    return r;
}
static __device__ __forceinline__ uint32_t hmax2z(uint32_t v) {
    uint32_t r;
    asm("max.f16x2 %0, %1, %2;" : "=r"(r) : "r"(v), "r"(0u));
    return r;
}
static __device__ __forceinline__ uint32_t hadd2(uint32_t a, uint32_t b) {
    uint32_t r;
    asm("add.f16x2 %0, %1, %2;" : "=r"(r) : "r"(a), "r"(b));
    return r;
}
static __device__ __forceinline__ void unpkh2(uint32_t v, float& lo, float& hi) {
    asm("{ .reg .f16 l, h; mov.b32 {l, h}, %2; cvt.f32.f16 %0, l; cvt.f32.f16 %1, h; }"
        : "=f"(lo), "=f"(hi) : "r"(v));
}
static __device__ __forceinline__ void ldsm4(uint32_t a[4], uint32_t addr) {
    asm volatile("ldmatrix.sync.aligned.m8n8.x4.shared.b16 {%0,%1,%2,%3}, [%4];"
                 : "=r"(a[0]), "=r"(a[1]), "=r"(a[2]), "=r"(a[3]) : "r"(addr));
}
static __device__ __forceinline__ void stsm4(uint32_t addr, uint32_t r0, uint32_t r1,
                                             uint32_t r2, uint32_t r3) {
    asm volatile("stmatrix.sync.aligned.m8n8.x4.shared.b16 [%0], {%1,%2,%3,%4};"
                 :: "r"(addr), "r"(r0), "r"(r1), "r"(r2), "r"(r3) : "memory");
}
static __device__ __forceinline__ void mma16816h(uint32_t c[2], const uint32_t a[4],
                                                 const uint32_t b[2]) {
    asm volatile(
        "mma.sync.aligned.m16n8k16.row.col.f16.f16.f16.f16 "
        "{%0,%1}, {%2,%3,%4,%5}, {%6,%7}, {%0,%1};"
        : "+r"(c[0]), "+r"(c[1])
        : "r"(a[0]), "r"(a[1]), "r"(a[2]), "r"(a[3]), "r"(b[0]), "r"(b[1]));
}
static __device__ __forceinline__ void sts128(uint32_t addr, uint32_t a, uint32_t b,
                                              uint32_t c, uint32_t d) {
    asm volatile("st.shared.v4.b32 [%0], {%1,%2,%3,%4};"
                 :: "r"(addr), "r"(a), "r"(b), "r"(c), "r"(d) : "memory");
}
static __device__ __forceinline__ void sts32(uint32_t addr, uint32_t v) {
    asm volatile("st.shared.b32 [%0], %1;" :: "r"(addr), "r"(v) : "memory");
}

extern "C" __global__ void __launch_bounds__(128, 4)
rnn_kernel(const float* __restrict__ x,
           const float* __restrict__ W_left, const float* __restrict__ W_right,
           const float* __restrict__ W_up,   const float* __restrict__ W_down,
           float* __restrict__ out)
{
    extern __shared__ char dsm[];
    const uint32_t base = (smem_u32(dsm) + 15u) & ~15u;
    const uint32_t P0 = base;              // step-0 state = f16 x (swizzled)
    const uint32_t P1 = base + BUFB;

    const int tid  = threadIdx.x;
    const int lane = tid & 31;
    const int warp = tid >> 5;             // 0..3, m0 = 48*warp
    const int gID  = lane >> 2;
    const int tg   = lane & 3;
    const int m0   = warp * 48;
    const int dir  = blockIdx.y;           // 0 = fwd(left/up), 1 = bwd(right/down)

    // --- geometry ---
    long inBase, outBase;
    int pixIn, pixOut, chBase;
    const float* Wg;
    {
        int l = blockIdx.x;
        if (l < 1536) {                            // horizontal row
            inBase  = (long)l * (192 * 64);
            outBase = (long)l * (192 * 256);
            pixIn = 64;  pixOut = 256;  chBase = 0;
            Wg = dir ? W_right : W_left;
        } else {                                    // vertical column
            int l2 = l - 1536;
            int b = l2 / 192, w = l2 % 192;
            inBase  = (long)b * (192 * 192 * 64)  + (long)w * 64;
            outBase = (long)b * (192 * 192 * 256) + (long)w * 256;
            pixIn = 192 * 64;  pixOut = 192 * 256;  chBase = 128;
            Wg = dir ? W_down : W_up;
        }
    }
    const float* xl = x + inBase;
    float* ol = out + outBase;

    // --- zero guard rows (rows 0 and 193 of both buffers) ---
    if (tid < 32) {
        sts32(P0 + tid * 4, 0);  sts32(P0 + 193 * 128 + tid * 4, 0);
        sts32(P1 + tid * 4, 0);  sts32(P1 + 193 * 128 + tid * 4, 0);
    }

    // --- load x (f16) into P0 rows 1..192, SW128-swizzled (step-0 state) ---
    #pragma unroll
    for (int p = 0; p < 6; p++) {
        int i = tid + p * 128;                  // 0..767
        int r = i >> 2;
        int c0 = (i & 3) * 16;                  // float col base
        const float* xp = xl + (long)r * pixIn + c0;
        uint32_t h[8];
        #pragma unroll
        for (int j = 0; j < 4; j++) {
            float4 v = *reinterpret_cast<const float4*>(xp + j * 4);
            h[2 * j]     = pkh2(v.x, v.y);
            h[2 * j + 1] = pkh2(v.z, v.w);
        }
        uint32_t rx = (uint32_t)(((r + 1) & 7) << 4);
        uint32_t rowb = P0 + (uint32_t)(r + 1) * 128;
        sts128(rowb + ((uint32_t)(c0 * 2) ^ rx),      h[0], h[1], h[2], h[3]);
        sts128(rowb + ((uint32_t)(c0 * 2 + 16) ^ rx), h[4], h[5], h[6], h[7]);
    }

    // --- B fragments (full n64) in registers, from gmem (L2-hot) ---
    uint32_t b[4][8][2];
    #pragma unroll
    for (int kc = 0; kc < 4; kc++)
        #pragma unroll
        for (int nt = 0; nt < 8; nt++) {
            int k0 = kc * 16 + 2 * tg;
            int n  = nt * 8 + gID;
            b[kc][nt][0] = pkh2(__ldg(&Wg[(k0)     * 64 + n]), __ldg(&Wg[(k0 + 1) * 64 + n]));
            b[kc][nt][1] = pkh2(__ldg(&Wg[(k0 + 8) * 64 + n]), __ldg(&Wg[(k0 + 9) * 64 + n]));
        }

    uint32_t acc[3][8][2];                     // packed f16x2 accumulators
    #pragma unroll
    for (int mt = 0; mt < 3; mt++)
        #pragma unroll
        for (int nt = 0; nt < 8; nt++) {
            acc[mt][nt][0] = 0u;  acc[mt][nt][1] = 0u;
        }

    // LDSM/STSM per-thread row/col decomposition
    const int lrow = (lane & 7) + ((lane >> 3) & 1) * 8;
    const int lcol = (lane >> 4) * 16;
    const int stRow = m0 + lrow + 1;
    const uint32_t rxS = (uint32_t)((stRow & 7) << 4);
    const uint32_t stBase = (uint32_t)(stRow * 128);
    const int shift = dir ? 1 : -1;            // fwd reads r-1, bwd reads r+1
    const int ldRow = m0 + lrow + shift + 1;
    const uint32_t rxL = (uint32_t)((ldRow & 7) << 4);
    const uint32_t ldBase = (uint32_t)(ldRow * 128);

    __syncthreads();

    uint32_t src = P0, dst = P1;

    #pragma unroll 1
    for (int s = 0; s < 8; s++) {
        const bool last = (s == 7);

        #pragma unroll
        for (int mt = 0; mt < 3; mt++) {
            uint32_t a[4][4];
            #pragma unroll
            for (int kc = 0; kc < 4; kc++)
                ldsm4(a[kc], src + ldBase + mt * 2048 +
                             ((uint32_t)(lcol + kc * 32) ^ rxL));

            uint32_t Cf[8][2];
            #pragma unroll
            for (int nt = 0; nt < 8; nt++) { Cf[nt][0] = 0u; Cf[nt][1] = 0u; }

            #pragma unroll
            for (int kc = 0; kc < 4; kc++)
                #pragma unroll
                for (int nt = 0; nt < 8; nt++)
                    mma16816h(Cf[nt], a[kc], b[kc][nt]);

            // relu in place
            #pragma unroll
            for (int nt = 0; nt < 8; nt++) {
                Cf[nt][0] = hmax2z(Cf[nt][0]);
                Cf[nt][1] = hmax2z(Cf[nt][1]);
            }
            // state store first (shortens path to the barrier) ...
            if (!last) {
                uint32_t sa = dst + stBase + mt * 2048;
                #pragma unroll
                for (int g = 0; g < 4; g++)
                    stsm4(sa + ((uint32_t)(lcol + g * 32) ^ rxS),
                          Cf[2 * g][0], Cf[2 * g][1],
                          Cf[2 * g + 1][0], Cf[2 * g + 1][1]);
            }
            // ... then accumulate
            #pragma unroll
            for (int nt = 0; nt < 8; nt++) {
                acc[mt][nt][0] = hadd2(acc[mt][nt][0], Cf[nt][0]);
                acc[mt][nt][1] = hadd2(acc[mt][nt][1], Cf[nt][1]);
            }
        }

        if (!last) __syncthreads();
        src = dst;
        dst = (dst == P0) ? P1 : P0;
    }

    // --- epilogue: out = x + acc ---
    const int cb = chBase + dir * 64;
    #pragma unroll
    for (int mt = 0; mt < 3; mt++) {
        #pragma unroll
        for (int hh = 0; hh < 2; hh++) {
            int gr = m0 + mt * 16 + gID + hh * 8;
            const float* xp = xl + (long)gr * pixIn;
            float* op = ol + (long)gr * pixOut + cb;
            #pragma unroll
            for (int nt = 0; nt < 8; nt++) {
                int col = nt * 8 + 2 * tg;
                float a0, a1;
                unpkh2(acc[mt][nt][hh], a0, a1);
                float2 xv = *reinterpret_cast<const float2*>(xp + col);
                *reinterpret_cast<float2*>(op + col) =
                    make_float2(xv.x + a0, xv.y + a1);
            }
        }
    }
}

extern "C" void kernel_launch(void* const* d_in, const int* in_sizes, int n_in,
                              void* d_out, int out_size)
{
    const float* x  = (const float*)d_in[0];
    const float* wl = (const float*)d_in[1];
    const float* wr = (const float*)d_in[2];
    const float* wu = (const float*)d_in[3];
    const float* wd = (const float*)d_in[4];
    float* out = (float*)d_out;

    cudaFuncSetAttribute(rnn_kernel, cudaFuncAttributeMaxDynamicSharedMemorySize, SMEM_DYN);
    dim3 grid(3072, 2);
    rnn_kernel<<<grid, 128, SMEM_DYN>>>(x, wl, wr, wu, wd, out);
}